// round 10
// baseline (speedup 1.0000x reference)
#include <cuda_runtime.h>

#define N_PILLARS 30000
#define WPB 8
#define GRID_S 592    // statsA: 4 blocks/SM * 148
#define GRID_F 444    // fusedC: 3 blocks/SM * 148, one wave
#define NM_F 960000.0f
#define LOG2E 1.44269504088896340736f
#define NPART 62

__device__ float2 g_k[N_PILLARS * 32];     // per (pillar,lane) K for channels (lane, lane+32)
__device__ float  g_part[GRID_S * NPART];  // per-block stat partials
__device__ float  g_ab[128];               // [0:64)=scale a, [64:128)=bias b

#define INFF __int_as_float(0x7f800000)

__device__ __forceinline__ float wredsum(float v) {
#pragma unroll
    for (int o = 16; o; o >>= 1) v += __shfl_xor_sync(0xffffffffu, v, o);
    return v;
}
__device__ __forceinline__ void wredsum2(float& a, float& b) {
#pragma unroll
    for (int o = 16; o; o >>= 1) {
        a += __shfl_xor_sync(0xffffffffu, a, o);
        b += __shfl_xor_sync(0xffffffffu, b, o);
    }
}
__device__ __forceinline__ float wredmax(float v) {
#pragma unroll
    for (int o = 16; o; o >>= 1) v = fmaxf(v, __shfl_xor_sync(0xffffffffu, v, o));
    return v;
}
__device__ __forceinline__ float wredmin(float v) {
#pragma unroll
    for (int o = 16; o; o >>= 1) v = fminf(v, __shfl_xor_sync(0xffffffffu, v, o));
    return v;
}
__device__ __forceinline__ float ex2a(float x) {
    float r; asm("ex2.approx.f32 %0, %1;" : "=f"(r) : "f"(x)); return r;
}

// entry e -> stage-index triple (value = st[ia]*st[ib]*st[ic])
// stage: [0..2]=cx,cy,cz  [3..5]=mx,my,mz  [6..9]=Sx,Sy,Sz,Sw  [10]=npf  [11]=exists
__device__ __forceinline__ void etriple(int e, int& ia, int& ib, int& ic) {
    if (e < 3)       { ia = e; ib = 10; ic = 11; }
    else if (e < 27) { int t = e - 3; ia = t >> 2; ib = 6 + (t & 3); ic = 11; }
    else {
        int t = e - 27; int a = 0;
        while (t >= 6 - a) { t -= 6 - a; a++; }
        ia = a; ib = a + t; ic = 10;
    }
}

// ---------------------------------------------------------------------------
// statsA: 2-pillar interleaved stats + K precompute (g_k)
// ---------------------------------------------------------------------------
__global__ __launch_bounds__(256, 4) void statsA_kernel(
    const float4* __restrict__ feat,
    const int*    __restrict__ npts,
    const int4*   __restrict__ coors,
    const float*  __restrict__ W)
{
    __shared__ float sh_st[WPB][24];    // two pillars x 12
    __shared__ float sh_e[WPB][48];
    __shared__ float sh_m[WPB][14];

    const int tid  = threadIdx.x;
    const int wid  = tid >> 5;
    const int lane = tid & 31;

    // per-lane channel coefficients for K (channels lane, lane+32)
    const int c0 = lane, c1 = lane + 32;
    const float P00 = W[c0] + W[448 + c0], P10 = W[64 + c0] + W[512 + c0], P20 = W[128 + c0] + W[576 + c0];
    const float Q00 = W[256 + c0], Q10 = W[320 + c0], Q20 = W[384 + c0];
    const float P01 = W[c1] + W[448 + c1], P11 = W[64 + c1] + W[512 + c1], P21 = W[128 + c1] + W[576 + c1];
    const float Q01 = W[256 + c1], Q11 = W[320 + c1], Q21 = W[384 + c1];

    int ia0, ib0, ic0, ia1, ib1, ic1;
    etriple(lane, ia0, ib0, ic0);
    const bool has1 = (lane < 16);
    etriple(has1 ? (32 + lane) : 0, ia1, ib1, ic1);

    float macc[10]; float sacc[4];
#pragma unroll
    for (int k = 0; k < 10; k++) macc[k] = 0.f;
#pragma unroll
    for (int k = 0; k < 4; k++) sacc[k] = 0.f;
    float ea0 = 0.f, ea1 = 0.f;

    const int S1 = GRID_S * WPB;   // 4736
    for (int n = blockIdx.x * WPB + wid; n < N_PILLARS; n += 2 * S1) {
        const int nb = n + S1;
        const bool hb = (nb < N_PILLARS);

        float4 fA = feat[n * 32 + lane];
        float4 fB = hb ? feat[nb * 32 + lane] : make_float4(0.f, 0.f, 0.f, 0.f);
        int npA = npts[n];
        int npB = hb ? npts[nb] : 1;
        int4 cA = coors[n];
        int4 cB = hb ? coors[nb] : make_int4(0, 0, 0, 0);

        float cxA = (float)cA.w * 0.2f + 0.1f;
        float cyA = (float)cA.z * 0.2f - 39.9f;
        float czA = (float)cA.y * 4.0f - 1.0f;
        float cxB = (float)cB.w * 0.2f + 0.1f;
        float cyB = (float)cB.z * 0.2f - 39.9f;
        float czB = (float)cB.y * 4.0f - 1.0f;

        // interleaved unmasked sums
        float UxA = fA.x, UyA = fA.y, UzA = fA.z;
        float UxB = fB.x, UyB = fB.y, UzB = fB.z;
        wredsum2(UxA, UxB); wredsum2(UyA, UyB); wredsum2(UzA, UzB);

        float npfA = (float)npA;
        float npfB = hb ? (float)npB : 0.f;
        float invA = __fdividef(1.0f, (float)npA);
        float invB = __fdividef(1.0f, (float)npB);
        float mxA = UxA * invA, myA = UyA * invA, mzA = UzA * invA;
        float mxB = UxB * invB, myB = UyB * invB, mzB = UzB * invB;

        bool vA = (lane < npA);
        bool vB = hb && (lane < npB);
        float XA = vA ? fA.x : 0.f, YA = vA ? fA.y : 0.f, ZA = vA ? fA.z : 0.f, WA = vA ? fA.w : 0.f;
        float XB = vB ? fB.x : 0.f, YB = vB ? fB.y : 0.f, ZB = vB ? fB.z : 0.f, WB = vB ? fB.w : 0.f;

        float SxA = XA, SyA = YA, SzA = ZA, SwA = WA;
        float SxB = XB, SyB = YB, SzB = ZB, SwB = WB;
        wredsum2(SxA, SxB); wredsum2(SyA, SyB); wredsum2(SzA, SzB); wredsum2(SwA, SwB);

        // per-lane quadratic stats (both pillars)
        macc[0] = fmaf(XA, XA, fmaf(XB, XB, macc[0]));
        macc[1] = fmaf(XA, YA, fmaf(XB, YB, macc[1]));
        macc[2] = fmaf(XA, ZA, fmaf(XB, ZB, macc[2]));
        macc[3] = fmaf(XA, WA, fmaf(XB, WB, macc[3]));
        macc[4] = fmaf(YA, YA, fmaf(YB, YB, macc[4]));
        macc[5] = fmaf(YA, ZA, fmaf(YB, ZB, macc[5]));
        macc[6] = fmaf(YA, WA, fmaf(YB, WB, macc[6]));
        macc[7] = fmaf(ZA, ZA, fmaf(ZB, ZB, macc[7]));
        macc[8] = fmaf(ZA, WA, fmaf(ZB, WB, macc[8]));
        macc[9] = fmaf(WA, WA, fmaf(WB, WB, macc[9]));
        sacc[0] += XA + XB; sacc[1] += YA + YB; sacc[2] += ZA + ZB; sacc[3] += WA + WB;

        // K for this lane's channels (both pillars) -> g_k
        float K0A = -fmaf(cxA, P00, fmaf(cyA, P10, fmaf(czA, P20, fmaf(mxA, Q00, fmaf(myA, Q10, mzA * Q20)))));
        float K1A = -fmaf(cxA, P01, fmaf(cyA, P11, fmaf(czA, P21, fmaf(mxA, Q01, fmaf(myA, Q11, mzA * Q21)))));
        g_k[n * 32 + lane] = make_float2(K0A, K1A);
        if (hb) {
            float K0B = -fmaf(cxB, P00, fmaf(cyB, P10, fmaf(czB, P20, fmaf(mxB, Q00, fmaf(myB, Q10, mzB * Q20)))));
            float K1B = -fmaf(cxB, P01, fmaf(cyB, P11, fmaf(czB, P21, fmaf(mxB, Q01, fmaf(myB, Q11, mzB * Q21)))));
            g_k[nb * 32 + lane] = make_float2(K0B, K1B);
        }

        // stage scalars (lane 0), vectorized
        __syncwarp();
        if (lane == 0) {
            float4* st4 = reinterpret_cast<float4*>(sh_st[wid]);
            st4[0] = make_float4(cxA, cyA, czA, mxA);
            st4[1] = make_float4(myA, mzA, SxA, SyA);
            st4[2] = make_float4(SzA, SwA, npfA, 1.0f);
            st4[3] = make_float4(cxB, cyB, czB, mxB);
            st4[4] = make_float4(myB, mzB, SxB, SyB);
            st4[5] = make_float4(SzB, SwB, npfB, hb ? 1.0f : 0.0f);
        }
        __syncwarp();

        const float* st = sh_st[wid];
        ea0 = fmaf(st[ia0] * st[ib0], st[ic0], ea0);
        ea0 = fmaf(st[12 + ia0] * st[12 + ib0], st[12 + ic0], ea0);
        if (has1) {
            ea1 = fmaf(st[ia1] * st[ib1], st[ic1], ea1);
            ea1 = fmaf(st[12 + ia1] * st[12 + ib1], st[12 + ic1], ea1);
        }
    }

    // block reduction of stats
    sh_e[wid][lane] = ea0;
    if (has1) sh_e[wid][32 + lane] = ea1;
#pragma unroll
    for (int k = 0; k < 10; k++) macc[k] = wredsum(macc[k]);
#pragma unroll
    for (int k = 0; k < 4; k++) sacc[k] = wredsum(sacc[k]);
    if (lane == 0) {
#pragma unroll
        for (int k = 0; k < 10; k++) sh_m[wid][k] = macc[k];
#pragma unroll
        for (int k = 0; k < 4; k++) sh_m[wid][10 + k] = sacc[k];
    }
    __syncthreads();
    if (tid < 48) {
        float s = 0.f;
#pragma unroll
        for (int w = 0; w < WPB; w++) s += sh_e[w][tid];
        g_part[blockIdx.x * NPART + tid] = s;
    } else if (tid < NPART) {
        float s = 0.f;
#pragma unroll
        for (int w = 0; w < WPB; w++) s += sh_m[w][tid - 48];
        g_part[blockIdx.x * NPART + tid] = s;
    }
}

// ---------------------------------------------------------------------------
// Pass 2: contract global stats per channel -> BN scale/bias
// ---------------------------------------------------------------------------
__global__ __launch_bounds__(1024) void pass2_kernel(
    const float* __restrict__ W,
    const float* __restrict__ gamma, const float* __restrict__ beta)
{
    __shared__ float shv[64][16];
    __shared__ float tot[NPART];
    int tid = threadIdx.x;
    int v = tid & 63, grp = tid >> 6;
    if (v < NPART) {
        float s = 0.f;
#pragma unroll 4
        for (int b = grp; b < GRID_S; b += 16) s += g_part[b * NPART + v];
        shv[v][grp] = s;
    }
    __syncthreads();
    if (tid < NPART) {
        float s = 0.f;
#pragma unroll
        for (int g = 0; g < 16; g++) s += shv[tid][g];
        tot[tid] = s;
    }
    __syncthreads();
    if (tid < 64) {
        int c = tid;
        float P0 = W[c] + W[448 + c], P1 = W[64 + c] + W[512 + c], P2 = W[128 + c] + W[576 + c];
        float Q0 = W[256 + c], Q1 = W[320 + c], Q2 = W[384 + c];
        float A[4] = { P0 + Q0, P1 + Q1, P2 + Q2, W[192 + c] };
        float R[6] = { P0, P1, P2, Q0, Q1, Q2 };
        float SG[4] = { tot[58], tot[59], tot[60], tot[61] };
        float T1[6] = { tot[0], tot[1], tot[2], tot[58], tot[59], tot[60] };

        float rs = A[0]*SG[0] + A[1]*SG[1] + A[2]*SG[2] + A[3]*SG[3]
                 - (R[0]*T1[0] + R[1]*T1[1] + R[2]*T1[2] + R[3]*T1[3] + R[4]*T1[4] + R[5]*T1[5]);

        float M[4][4];
        M[0][0]=tot[48]; M[0][1]=M[1][0]=tot[49]; M[0][2]=M[2][0]=tot[50]; M[0][3]=M[3][0]=tot[51];
        M[1][1]=tot[52]; M[1][2]=M[2][1]=tot[53]; M[1][3]=M[3][1]=tot[54];
        M[2][2]=tot[55]; M[2][3]=M[3][2]=tot[56]; M[3][3]=tot[57];
        float quadA = 0.f;
#pragma unroll
        for (int a = 0; a < 4; a++) {
            float h = 0.f;
#pragma unroll
            for (int b = 0; b < 4; b++) h += M[a][b] * A[b];
            quadA += A[a] * h;
        }
        float cross = 0.f;
#pragma unroll
        for (int b = 0; b < 4; b++) {
            float vb = 0.f;
#pragma unroll
            for (int a = 0; a < 6; a++) vb += R[a] * tot[3 + a * 4 + b];
            cross += vb * A[b];
        }
        float T3[6][6];
        int idx = 27;
#pragma unroll
        for (int a = 0; a < 6; a++)
#pragma unroll
            for (int b = a; b < 6; b++) { T3[a][b] = T3[b][a] = tot[idx]; idx++; }
        float quadR = 0.f;
#pragma unroll
        for (int a = 0; a < 6; a++) {
            float h = 0.f;
#pragma unroll
            for (int b = 0; b < 6; b++) h += T3[a][b] * R[b];
            quadR += R[a] * h;
        }
        float rq = quadA - 2.0f * cross + quadR;
        float mean = rs * (1.0f / NM_F);
        float var  = rq * (1.0f / NM_F) - mean * mean;
        float a = gamma[c] * rsqrtf(var + 1e-3f);
        g_ab[c] = a;
        g_ab[64 + c] = fmaf(-mean, a, beta[c]);
    }
}

// ---------------------------------------------------------------------------
// fusedC: attention (in-register weights) + BN-folded channel loop -> out
// K preloaded from g_k; no coors, no mean reductions.
// ---------------------------------------------------------------------------
__global__ __launch_bounds__(256, 3) void fusedC_kernel(
    const float4* __restrict__ feat,
    const int*    __restrict__ npts,
    const float*  __restrict__ W,
    const float*  __restrict__ wq, const float* __restrict__ wk,
    const float*  __restrict__ wv, const float* __restrict__ wo,
    const float*  __restrict__ bq, const float* __restrict__ bk,
    const float*  __restrict__ bv, const float* __restrict__ bo,
    float*        __restrict__ out)
{
    __shared__ float  shw[48];
    __shared__ float4 sh_kva[WPB][32];   // {k0,v0,k1,v1}
    __shared__ float2 sh_kvb[WPB][32];   // {k2,v2}
    __shared__ float4 sh_p[WPB][32];
    __shared__ float  sh_wt[WPB][32];

    const int tid  = threadIdx.x;
    const int wid  = tid >> 5;
    const int lane = tid & 31;

    if (tid < 9) { shw[tid] = wq[tid]; shw[9 + tid] = wk[tid]; shw[18 + tid] = wv[tid]; shw[27 + tid] = wo[tid]; }
    if (tid < 3) { shw[36 + tid] = bq[tid]; shw[39 + tid] = bk[tid]; shw[42 + tid] = bv[tid]; shw[45 + tid] = bo[tid]; }
    __syncthreads();

    const int c0 = lane, c1 = lane + 32;
    const float sa0 = g_ab[c0], sb0 = g_ab[64 + c0];
    const float sa1 = g_ab[c1], sb1 = g_ab[64 + c1];

    // BN-folded channel coefficients
    const float B00 = sa0 * (W[c0] + W[448 + c0] + W[256 + c0]);
    const float B10 = sa0 * (W[64 + c0] + W[512 + c0] + W[320 + c0]);
    const float B20 = sa0 * (W[128 + c0] + W[576 + c0] + W[384 + c0]);
    const float b30 = sa0 * W[192 + c0];
    const float B01 = sa1 * (W[c1] + W[448 + c1] + W[256 + c1]);
    const float B11 = sa1 * (W[64 + c1] + W[512 + c1] + W[320 + c1]);
    const float B21 = sa1 * (W[128 + c1] + W[576 + c1] + W[384 + c1]);
    const float b31 = sa1 * W[192 + c1];

    const float ym0 = fmaxf(sb0, 0.01f * sb0);
    const float ym1 = fmaxf(sb1, 0.01f * sb1);

    const int stride = GRID_F * WPB;   // 3552
    int n = blockIdx.x * WPB + wid;

    float4 f; float2 K2; int np;
    if (n < N_PILLARS) {
        f  = feat[n * 32 + lane];
        K2 = g_k[n * 32 + lane];
        np = npts[n];
    }

    while (n < N_PILLARS) {
        const int n2 = n + stride;
        float4 f2; float2 K22; int np2;
        if (n2 < N_PILLARS) {
            f2  = feat[n2 * 32 + lane];
            K22 = g_k[n2 * 32 + lane];
            np2 = npts[n2];
        }

        // ---- q,k,v ----
        float q0 = fmaf(f.x, shw[0], fmaf(f.y, shw[3], fmaf(f.z, shw[6], shw[36])));
        float q1 = fmaf(f.x, shw[1], fmaf(f.y, shw[4], fmaf(f.z, shw[7], shw[37])));
        float q2 = fmaf(f.x, shw[2], fmaf(f.y, shw[5], fmaf(f.z, shw[8], shw[38])));
        float k0 = fmaf(f.x, shw[9],  fmaf(f.y, shw[12], fmaf(f.z, shw[15], shw[39])));
        float k1 = fmaf(f.x, shw[10], fmaf(f.y, shw[13], fmaf(f.z, shw[16], shw[40])));
        float k2 = fmaf(f.x, shw[11], fmaf(f.y, shw[14], fmaf(f.z, shw[17], shw[41])));
        float v0 = fmaf(f.x, shw[18], fmaf(f.y, shw[21], fmaf(f.z, shw[24], shw[42])));
        float v1 = fmaf(f.x, shw[19], fmaf(f.y, shw[22], fmaf(f.z, shw[25], shw[43])));
        float v2 = fmaf(f.x, shw[20], fmaf(f.y, shw[23], fmaf(f.z, shw[26], shw[44])));
        float qs0 = q0 * LOG2E, qs1 = q1 * LOG2E, qs2 = q2 * LOG2E;

        __syncwarp();   // prior iteration's smem readers done
        sh_kva[wid][lane] = make_float4(k0, v0, k1, v1);
        sh_kvb[wid][lane] = make_float2(k2, v2);
        sh_p[wid][lane]   = f;
        __syncwarp();

        // ---- exp loop ----
        float l0 = 0.f, l1 = 0.f, l2 = 0.f, a0 = 0.f, a1 = 0.f, a2 = 0.f;
#pragma unroll
        for (int j = 0; j < 32; j++) {
            float4 kva = sh_kva[wid][j];
            float2 kvb = sh_kvb[wid][j];
            float e0 = ex2a(qs0 * kva.x);
            float e1 = ex2a(qs1 * kva.z);
            float e2 = ex2a(qs2 * kvb.x);
            l0 += e0; l1 += e1; l2 += e2;
            a0 = fmaf(e0, kva.y, a0);
            a1 = fmaf(e1, kva.w, a1);
            a2 = fmaf(e2, kvb.y, a2);
        }
        float o0 = __fdividef(a0, l0);
        float o1 = __fdividef(a1, l1);
        float o2 = __fdividef(a2, l2);
        float t0 = fmaf(o0, shw[27], fmaf(o1, shw[30], fmaf(o2, shw[33], shw[45])));
        float t1 = fmaf(o0, shw[28], fmaf(o1, shw[31], fmaf(o2, shw[34], shw[46])));
        float t2 = fmaf(o0, shw[29], fmaf(o1, shw[32], fmaf(o2, shw[35], shw[47])));
        float ma = fmaxf(t0, fmaxf(t1, t2));
        float S = wredsum(ma);
        float wt = __fdividef(ma, S);

        sh_wt[wid][lane] = wt;
        __syncwarp();

        float wmx = wredmax((lane >= np) ? wt : -INFF);
        float wmn = wredmin((lane >= np) ? wt :  INFF);

        const float Kb0 = fmaf(sa0, K2.x, sb0);
        const float Kb1 = fmaf(sa1, K2.y, sb1);

        float fm0 = -INFF, fa0 = -INFF, fm1 = -INFF, fa1 = -INFF;
        if (np < 32) {
            fm0 = ym0;  fa0 = (ym0 >= 0.f) ? ym0 * wmx : ym0 * wmn;
            fm1 = ym1;  fa1 = (ym1 >= 0.f) ? ym1 * wmx : ym1 * wmn;
        }
#pragma unroll 4
        for (int i = 0; i < np; i++) {
            float4 p = sh_p[wid][i];
            float w  = sh_wt[wid][i];
            float y0 = fmaf(p.x, B00, fmaf(p.y, B10, fmaf(p.z, B20, fmaf(p.w, b30, Kb0))));
            y0 = fmaxf(y0, 0.01f * y0);
            fm0 = fmaxf(fm0, y0);
            fa0 = fmaxf(fa0, w * y0);
            float y1 = fmaf(p.x, B01, fmaf(p.y, B11, fmaf(p.z, B21, fmaf(p.w, b31, Kb1))));
            y1 = fmaxf(y1, 0.01f * y1);
            fm1 = fmaxf(fm1, y1);
            fa1 = fmaxf(fa1, w * y1);
        }
        out[n * 64 + c0] = 0.5f * (fa0 + fm0);
        out[n * 64 + c1] = 0.5f * (fa1 + fm1);

        n = n2; f = f2; K2 = K22; np = np2;
    }
}

// ---------------------------------------------------------------------------
extern "C" void kernel_launch(void* const* d_in, const int* in_sizes, int n_in,
                              void* d_out, int out_size)
{
    const float4* feat  = (const float4*)d_in[0];
    const int*    np    = (const int*)   d_in[1];
    const int4*   co    = (const int4*)  d_in[2];
    const float*  W     = (const float*) d_in[3];
    const float*  gamma = (const float*) d_in[4];
    const float*  beta  = (const float*) d_in[5];
    const float*  wq    = (const float*) d_in[6];
    const float*  wk    = (const float*) d_in[7];
    const float*  wv    = (const float*) d_in[8];
    const float*  wo    = (const float*) d_in[9];
    const float*  bq    = (const float*) d_in[10];
    const float*  bk    = (const float*) d_in[11];
    const float*  bv    = (const float*) d_in[12];
    const float*  bo    = (const float*) d_in[13];
    float* out = (float*)d_out;

    statsA_kernel<<<GRID_S, 256>>>(feat, np, co, W);
    pass2_kernel<<<1, 1024>>>(W, gamma, beta);
    fusedC_kernel<<<GRID_F, 256>>>(feat, np, W, wq, wk, wv, wo, bq, bk, bv, bo, out);
}